// round 10
// baseline (speedup 1.0000x reference)
#include <cuda_runtime.h>
#include <math.h>

// ---------------- problem constants ----------------
#define Bc   16
#define Tc   1536
#define Vc   64
#define F1c  16
#define Hc   4
#define FOc  8
#define F2c  32
#define K1c  32
#define K3c  16
#define NG   4          // graphs per block (was 8)
#define EMAX 512
#define NTHR 256

// xs row stride: window NG-1+32 = 35, pad to 36
#define XROW 36
#define XS_F (Vc * XROW)
// hbuf row stride (floats)
#define HSTR 36
#define HG   (Vc * HSTR)
// packed exp-table: per graph, [head][66] float2
#define EST_F (Hc * 66 * 2)

// ---------------- device scratch ----------------
__device__ float d_weff[32 * 32];   // [k][ho]
__device__ float d_cvec[32];
__device__ float d_scale2[32], d_shift2[32], d_scale3[32], d_shift3[32];
__device__ int   d_off[Vc + 1];
__device__ int   d_srcs[EMAX];
__device__ float d_gbuf[Bc * Tc * F2c];

// ---------------- packed f32x2 helpers ----------------
typedef unsigned long long ull;
__device__ __forceinline__ ull pack2(float lo, float hi) {
    ull r;
    asm("mov.b64 %0, {%1, %2};" : "=l"(r) : "f"(lo), "f"(hi));
    return r;
}
__device__ __forceinline__ void fma2(ull& d, ull a, ull b) {
    asm("fma.rn.f32x2 %0, %1, %2, %0;" : "+l"(d) : "l"(a), "l"(b));
}
__device__ __forceinline__ void unpack2(ull v, float& lo, float& hi) {
    asm("mov.b64 {%0, %1}, %2;" : "=f"(lo), "=f"(hi) : "l"(v));
}

// ---------------- setup (R5 version) ----------------
__global__ void setup_kernel(const float* __restrict__ conv1_w,
                             const float* __restrict__ bn1_g, const float* __restrict__ bn1_b,
                             const float* __restrict__ bn1_m, const float* __restrict__ bn1_v,
                             const float* __restrict__ gat_w,
                             const float* __restrict__ bn2_g, const float* __restrict__ bn2_b,
                             const float* __restrict__ bn2_m, const float* __restrict__ bn2_v,
                             const float* __restrict__ bn3_g, const float* __restrict__ bn3_b,
                             const float* __restrict__ bn3_m, const float* __restrict__ bn3_v,
                             const int* __restrict__ edge_index, int E) {
    __shared__ float sc1[F1c], sh1[F1c];
    __shared__ float s_c1[F1c * K1c];
    __shared__ float s_gw[F1c * 32];
    __shared__ int sedge[2 * EMAX];
    __shared__ int cnt4[Vc][4];
    __shared__ int soff[Vc + 1];
    int tid = threadIdx.x;

    for (int i = tid; i < 2 * E; i += blockDim.x) sedge[i] = edge_index[i];
    for (int i = tid; i < F1c * K1c; i += blockDim.x) s_c1[i] = conv1_w[i];
    for (int i = tid; i < F1c * 32; i += blockDim.x) s_gw[i] = gat_w[i];
    if (tid < F1c) {
        float s = bn1_g[tid] * rsqrtf(bn1_v[tid] + 1e-5f);
        sc1[tid] = s;
        sh1[tid] = bn1_b[tid] - bn1_m[tid] * s;
    }
    if (tid < F2c) {
        float s2 = bn2_g[tid] * rsqrtf(bn2_v[tid] + 1e-5f);
        d_scale2[tid] = s2; d_shift2[tid] = bn2_b[tid] - bn2_m[tid] * s2;
        float s3 = bn3_g[tid] * rsqrtf(bn3_v[tid] + 1e-5f);
        d_scale3[tid] = s3; d_shift3[tid] = bn3_b[tid] - bn3_m[tid] * s3;
    }
    __syncthreads();
    for (int i = tid; i < K1c * 32; i += blockDim.x) {
        int k = i >> 5, ho = i & 31;
        float s = 0.f;
        #pragma unroll
        for (int f = 0; f < F1c; f++)
            s = fmaf(s_gw[f * 32 + ho] * sc1[f], s_c1[f * K1c + k], s);
        d_weff[i] = s;
    }
    if (tid < 32) {
        float s = 0.f;
        #pragma unroll
        for (int f = 0; f < F1c; f++) s = fmaf(s_gw[f * 32 + tid], sh1[f], s);
        d_cvec[tid] = s;
    }
    const int* src = sedge;
    const int* dst = sedge + E;
    const int qsz = (E + 3) >> 2;
    const int v = tid >> 2, q = tid & 3;
    const int lo = q * qsz;
    const int hi = min(E, lo + qsz);
    {
        int c = 0;
        for (int e = lo; e < hi; e++) c += (dst[e] == v);
        cnt4[v][q] = c;
    }
    __syncthreads();
    if (tid == 0) {
        int off = 0;
        for (int vv = 0; vv < Vc; vv++) {
            soff[vv] = off;
            off += cnt4[vv][0] + cnt4[vv][1] + cnt4[vv][2] + cnt4[vv][3];
        }
        soff[Vc] = off;
    }
    __syncthreads();
    if (tid <= Vc) d_off[tid] = soff[tid];
    {
        int p = soff[v];
        for (int qq = 0; qq < 4; qq++) if (qq < q) p += cnt4[v][qq];
        for (int e = lo; e < hi; e++)
            if (dst[e] == v) d_srcs[p++] = src[e];
    }
}

// ---------------- main: NG=4, 256 thr, 4 blocks/SM (regs forced <=64) ----------------
// smem floats: xs[2304] (ed aliased here after conv) | const 96 | hbuf[4*2304] | est[4*528]
//              ints: soff[65] srcs[512]
#define SM_FLOATS (XS_F + 96 + NG * HG + NG * EST_F)
#define MAIN_SMEM (SM_FLOATS * 4 + (Vc + 1 + EMAX) * 4)

__global__ void __launch_bounds__(NTHR, 4)
main_kernel(const float* __restrict__ x,
            const float* __restrict__ asrc_g,
            const float* __restrict__ adst_g,
            const float* __restrict__ bias_g,
            int E) {
    extern __shared__ float sm[];
    float* xs    = sm;                    // conv phase; ed aliased here in GAT phase
    float* sasrc = xs + XS_F;
    float* sadst = sasrc + 32;
    float* sbias = sadst + 32;
    float* hbuf  = sbias + 32;            // [g][v][HSTR]
    float* est_s = hbuf + NG * HG;        // [g][head][66] float2 {E1,E5}
    int*   soff  = (int*)(est_s + NG * EST_F);
    int*   ssrc  = soff + (Vc + 1);
    float* ed_s  = xs;                    // alias: [g][v*4+head], valid after conv sync

    const int tid = threadIdx.x;
    const int bx  = blockIdx.x;
    const int b   = bx / (Tc / NG);
    const int t0  = (bx % (Tc / NG)) * NG;

    for (int idx = tid; idx < Vc * XROW; idx += NTHR) {
        int v = idx / XROW, j = idx - v * XROW;
        int t = t0 - 15 + j;
        float val = 0.f;
        if (j < NG + 31 && t >= 0 && t < Tc) val = x[(b * Vc + v) * Tc + t];
        xs[idx] = val;
    }
    if (tid < 32) {
        sasrc[tid] = asrc_g[tid];
        sadst[tid] = adst_g[tid];
        sbias[tid] = bias_g[tid];
    }
    for (int i = tid; i < Vc + 1; i += NTHR) soff[i] = d_off[i];
    for (int i = tid; i < E; i += NTHR) ssrc[i] = d_srcs[i];
    __syncthreads();

    // ---- conv via FFMA2: 8 slots x 8 rows, 4 g per row, 5 accumulators ----
    {
        const int ho = tid & 31;
        const int slot = tid >> 5;          // 0..7
        float w[K1c];
        #pragma unroll
        for (int k = 0; k < K1c; k++) w[k] = d_weff[k * 32 + ho];
        const float cv = d_cvec[ho];
        const ull cvu = pack2(cv, cv);
        #pragma unroll 1
        for (int i = 0; i < 8; i++) {
            const int v = slot * 8 + i;
            const float* xr = xs + v * XROW;
            ull pe[18];
            #pragma unroll
            for (int j = 0; j < 4; j++) pe[j] = *(const ull*)(xr + 2 * j);
            ull acc2[2], accO[3];
            acc2[0] = cvu; acc2[1] = cvu;
            accO[0] = 0ULL; accO[1] = 0ULL; accO[2] = 0ULL;
            #pragma unroll
            for (int kh = 0; kh < 16; kh++) {
                if (kh < 14) pe[kh + 4] = *(const ull*)(xr + 2 * (kh + 4));
                const ull w0 = pack2(w[2 * kh],     w[2 * kh]);
                const ull w1 = pack2(w[2 * kh + 1], w[2 * kh + 1]);
                fma2(acc2[0], w0, pe[kh]);
                fma2(acc2[1], w0, pe[kh + 1]);
                fma2(accO[0], w1, pe[kh]);
                fma2(accO[1], w1, pe[kh + 1]);
                fma2(accO[2], w1, pe[kh + 2]);
            }
            float e0l, e0h, e1l, e1h;
            float o0l, o0h, o1l, o1h, o2l, o2h;
            unpack2(acc2[0], e0l, e0h);
            unpack2(acc2[1], e1l, e1h);
            unpack2(accO[0], o0l, o0h);
            unpack2(accO[1], o1l, o1h);
            unpack2(accO[2], o2l, o2h);
            hbuf[0 * HG + v * HSTR + ho] = e0l + o0h;
            hbuf[1 * HG + v * HSTR + ho] = e0h + o1l;
            hbuf[2 * HG + v * HSTR + ho] = e1l + o1h;
            hbuf[3 * HG + v * HSTR + ho] = e1h + o2l;
        }
    }
    __syncthreads();

    // ---- GAT (warps 0..3), exp factored out of the edge chain ----
    const int warp = tid >> 5, lane = tid & 31;
    if (warp < NG) {
        float*  h   = hbuf + warp * HG;
        float2* est = (float2*)(est_s + warp * EST_F);   // [head*66 + v]
        float*  ed  = ed_s + warp * 256;                 // [v*4+head]

        #pragma unroll
        for (int i = 0; i < 8; i++) {
            int p = lane + 32 * i;
            int head = p & 3, v = p >> 2;
            const float4* hv4 = (const float4*)(h + v * HSTR + head * 8);
            const float4* as4 = (const float4*)(sasrc + head * 8);
            const float4* ad4 = (const float4*)(sadst + head * 8);
            float4 h0 = hv4[0], h1 = hv4[1];
            float4 a0 = as4[0], a1 = as4[1];
            float4 d0 = ad4[0], d1 = ad4[1];
            float se = h0.x * a0.x + h0.y * a0.y + h0.z * a0.z + h0.w * a0.w
                     + h1.x * a1.x + h1.y * a1.y + h1.z * a1.z + h1.w * a1.w;
            float sd = h0.x * d0.x + h0.y * d0.y + h0.z * d0.z + h0.w * d0.w
                     + h1.x * d1.x + h1.y * d1.y + h1.z * d1.z + h1.w * d1.w;
            est[head * 66 + v] = make_float2(__expf(se), __expf(0.2f * se));
            ed[v * 4 + head]   = sd;
        }
        __syncwarp();

        float macc[8];
        #pragma unroll
        for (int o = 0; o < 8; o++) macc[o] = 0.f;
        const int head = lane & 3;
        const float2* estb = est + head * 66;
        for (int i = 0; i < 8; i++) {
            const int d = (lane >> 2) + 8 * i;
            const float edv = ed[d * 4 + head];
            const float D1 = __expf(edv);
            const float D5 = __expf(0.2f * edv);
            const int beg = soff[d], end = soff[d + 1];
            float den = 0.f;
            float a0 = 0.f, a1 = 0.f, a2 = 0.f, a3 = 0.f;
            float a4 = 0.f, a5 = 0.f, a6 = 0.f, a7 = 0.f;
            for (int e = beg; e < end; e++) {
                int s = ssrc[e];
                float2 Ev = estb[s];
                float p = Ev.x * D1;           // exp(es+ed)
                float q = Ev.y * D5;           // exp(0.2*(es+ed))
                float wexp = p > 1.f ? p : q;  // leaky-relu in exp domain
                den += wexp;
                const float4* hs4 = (const float4*)(h + s * HSTR + head * 8);
                float4 q0 = hs4[0], q1 = hs4[1];
                a0 = fmaf(wexp, q0.x, a0); a1 = fmaf(wexp, q0.y, a1);
                a2 = fmaf(wexp, q0.z, a2); a3 = fmaf(wexp, q0.w, a3);
                a4 = fmaf(wexp, q1.x, a4); a5 = fmaf(wexp, q1.y, a5);
                a6 = fmaf(wexp, q1.z, a6); a7 = fmaf(wexp, q1.w, a7);
            }
            float inv = __frcp_rn(den);
            macc[0] = fmaf(a0, inv, macc[0]); macc[1] = fmaf(a1, inv, macc[1]);
            macc[2] = fmaf(a2, inv, macc[2]); macc[3] = fmaf(a3, inv, macc[3]);
            macc[4] = fmaf(a4, inv, macc[4]); macc[5] = fmaf(a5, inv, macc[5]);
            macc[6] = fmaf(a6, inv, macc[6]); macc[7] = fmaf(a7, inv, macc[7]);
        }
        #pragma unroll
        for (int o = 0; o < 8; o++) {
            macc[o] += __shfl_xor_sync(0xffffffffu, macc[o], 4);
            macc[o] += __shfl_xor_sync(0xffffffffu, macc[o], 8);
            macc[o] += __shfl_xor_sync(0xffffffffu, macc[o], 16);
        }
        if (lane < 4) {
            const int t = t0 + warp;
            float* gout = d_gbuf + (b * Tc + t) * 32 + head * 8;
            #pragma unroll
            for (int o = 0; o < 8; o++)
                gout[o] = macc[o] * (1.0f / 64.0f) + sbias[head * 8 + o];
        }
    }
}

// ---------------- tail ----------------
#define TP 192
#define TAIL_SMEM ((F2c * F2c * K3c + F2c * 40 + F2c * 24) * 4)

__global__ void __launch_bounds__(256)
tail_kernel(const float* __restrict__ conv3_w, float* __restrict__ out) {
    extern __shared__ float sm[];
    float* w3s   = sm;
    float* ptile = w3s + F2c * F2c * K3c;
    float* ytile = ptile + F2c * 40;

    const int tid = threadIdx.x;
    const int b = blockIdx.x;
    const int tile = blockIdx.y;
    const int tc0 = tile * 24;

    for (int i = tid; i < F2c * F2c * K3c; i += 256) w3s[i] = conv3_w[i];
    for (int i = tid; i < F2c * 40; i += 256) {
        int fi = i & 31, j = i >> 5;
        int tc = tc0 - 7 + j;
        float val = 0.f;
        if (j < 39 && tc >= 0 && tc < TP) {
            float scv = d_scale2[fi], shv = d_shift2[fi];
            float s = 0.f;
            #pragma unroll
            for (int r = 0; r < 8; r++) {
                float gv = fmaf(scv, d_gbuf[(b * Tc + tc * 8 + r) * 32 + fi], shv);
                s += gv > 0.f ? gv : (__expf(gv) - 1.f);
            }
            val = s * 0.125f;
        }
        ptile[fi * 40 + j] = val;
    }
    __syncthreads();

    for (int oidx = tid; oidx < F2c * 24; oidx += 256) {
        int fo = oidx / 24;
        int tcl = oidx - fo * 24;
        float acc = 0.f;
        for (int fi = 0; fi < F2c; fi++) {
            const float* wr = w3s + (fo * 32 + fi) * 16;
            const float* pr = ptile + fi * 40 + tcl;
            #pragma unroll
            for (int k = 0; k < K3c; k++) acc = fmaf(wr[k], pr[k], acc);
        }
        float z = fmaf(d_scale3[fo], acc, d_shift3[fo]);
        z = z > 0.f ? z : (__expf(z) - 1.f);
        ytile[fo * 24 + tcl] = z;
    }
    __syncthreads();

    for (int i = tid; i < F2c * 6; i += 256) {
        int fo = i / 6, tl = i - fo * 6;
        const float* yr = ytile + fo * 24 + tl * 4;
        float s = 0.25f * (yr[0] + yr[1] + yr[2] + yr[3]);
        out[(b * 32 + fo) * 48 + tile * 6 + tl] = s;
    }
}

// pad launches: keep main_kernel at captured launch index 3
__global__ void prof_pad_kernel() {}

// ---------------- launch ----------------
extern "C" void kernel_launch(void* const* d_in, const int* in_sizes, int n_in,
                              void* d_out, int out_size) {
    const float* x        = (const float*)d_in[0];
    const float* conv1_w  = (const float*)d_in[1];
    const float* bn1_g    = (const float*)d_in[2];
    const float* bn1_b    = (const float*)d_in[3];
    const float* bn1_m    = (const float*)d_in[4];
    const float* bn1_v    = (const float*)d_in[5];
    const float* gat_w    = (const float*)d_in[6];
    const float* gat_asrc = (const float*)d_in[7];
    const float* gat_adst = (const float*)d_in[8];
    const float* gat_bias = (const float*)d_in[9];
    const float* bn2_g    = (const float*)d_in[10];
    const float* bn2_b    = (const float*)d_in[11];
    const float* bn2_m    = (const float*)d_in[12];
    const float* bn2_v    = (const float*)d_in[13];
    const float* conv3_w  = (const float*)d_in[14];
    const float* bn3_g    = (const float*)d_in[15];
    const float* bn3_b    = (const float*)d_in[16];
    const float* bn3_m    = (const float*)d_in[17];
    const float* bn3_v    = (const float*)d_in[18];
    const int*   edge_idx = (const int*)d_in[19];
    int E = in_sizes[19] / 2;
    if (E > EMAX) E = EMAX;

    cudaFuncSetAttribute(main_kernel, cudaFuncAttributeMaxDynamicSharedMemorySize, MAIN_SMEM);
    cudaFuncSetAttribute(tail_kernel, cudaFuncAttributeMaxDynamicSharedMemorySize, TAIL_SMEM);

    setup_kernel<<<1, 256>>>(conv1_w, bn1_g, bn1_b, bn1_m, bn1_v, gat_w,
                             bn2_g, bn2_b, bn2_m, bn2_v,
                             bn3_g, bn3_b, bn3_m, bn3_v, edge_idx, E);
    prof_pad_kernel<<<1, 1>>>();
    prof_pad_kernel<<<1, 1>>>();
    main_kernel<<<Bc * (Tc / NG), NTHR, MAIN_SMEM>>>(x, gat_asrc, gat_adst, gat_bias, E);
    tail_kernel<<<dim3(Bc, 8), 256, TAIL_SMEM>>>(conv3_w, (float*)d_out);
}

// round 11
// speedup vs baseline: 1.1807x; 1.1807x over previous
#include <cuda_runtime.h>
#include <math.h>

// ---------------- problem constants ----------------
#define Bc   16
#define Tc   1536
#define Vc   64
#define F1c  16
#define Hc   4
#define FOc  8
#define F2c  32
#define K1c  32
#define K3c  16
#define NG   8
#define EMAX 512
#define NTHR 384

#define XROW 40
#define XS_F (Vc * XROW)
// h1 (16-ch) row stride
#define H16  20
#define HG16 (Vc * H16)     // 1280 floats per graph

// ---------------- device scratch ----------------
__device__ float d_wc[K1c * 16];   // [k][f]  bn-folded conv weights
__device__ float d_bc[16];         // bn shift per f
__device__ float d_A[64];          // [head][16]  W·a_src folded
__device__ float d_Dv[64];         // [head][16]  W·a_dst folded
__device__ float d_scale2[32], d_shift2[32], d_scale3[32], d_shift3[32];
__device__ int   d_off[Vc + 1];
__device__ int   d_srcs[EMAX];
__device__ int   d_roff[Vc + 1];
__device__ int   d_rdst[EMAX];
__device__ float d_gbuf[Bc * Tc * F2c];

// ---------------- packed f32x2 helpers ----------------
typedef unsigned long long ull;
__device__ __forceinline__ ull pack2(float lo, float hi) {
    ull r;
    asm("mov.b64 %0, {%1, %2};" : "=l"(r) : "f"(lo), "f"(hi));
    return r;
}
__device__ __forceinline__ void fma2(ull& d, ull a, ull b) {
    asm("fma.rn.f32x2 %0, %1, %2, %0;" : "+l"(d) : "l"(a), "l"(b));
}
__device__ __forceinline__ void unpack2(ull v, float& lo, float& hi) {
    asm("mov.b64 {%0, %1}, %2;" : "=f"(lo), "=f"(hi) : "l"(v));
}

// ---------------- setup ----------------
__global__ void setup_kernel(const float* __restrict__ conv1_w,
                             const float* __restrict__ bn1_g, const float* __restrict__ bn1_b,
                             const float* __restrict__ bn1_m, const float* __restrict__ bn1_v,
                             const float* __restrict__ gat_w,
                             const float* __restrict__ gat_asrc, const float* __restrict__ gat_adst,
                             const float* __restrict__ bn2_g, const float* __restrict__ bn2_b,
                             const float* __restrict__ bn2_m, const float* __restrict__ bn2_v,
                             const float* __restrict__ bn3_g, const float* __restrict__ bn3_b,
                             const float* __restrict__ bn3_m, const float* __restrict__ bn3_v,
                             const int* __restrict__ edge_index, int E) {
    __shared__ float sc1[F1c], sh1[F1c];
    __shared__ float s_gw[F1c * 32];
    __shared__ int sedge[2 * EMAX];
    __shared__ int cnt4[Vc][4], rcnt4[Vc][4];
    __shared__ int soff[Vc + 1], rsoff[Vc + 1];
    int tid = threadIdx.x;

    for (int i = tid; i < 2 * E; i += blockDim.x) sedge[i] = edge_index[i];
    for (int i = tid; i < F1c * 32; i += blockDim.x) s_gw[i] = gat_w[i];
    if (tid < F1c) {
        float s = bn1_g[tid] * rsqrtf(bn1_v[tid] + 1e-5f);
        sc1[tid] = s;
        sh1[tid] = bn1_b[tid] - bn1_m[tid] * s;
    }
    if (tid < F2c) {
        float s2 = bn2_g[tid] * rsqrtf(bn2_v[tid] + 1e-5f);
        d_scale2[tid] = s2; d_shift2[tid] = bn2_b[tid] - bn2_m[tid] * s2;
        float s3 = bn3_g[tid] * rsqrtf(bn3_v[tid] + 1e-5f);
        d_scale3[tid] = s3; d_shift3[tid] = bn3_b[tid] - bn3_m[tid] * s3;
    }
    __syncthreads();
    // bn-folded conv weights: wc[k][f] = sc1[f] * conv1_w[f][k]
    for (int i = tid; i < K1c * 16; i += blockDim.x) {
        int k = i >> 4, f = i & 15;
        d_wc[i] = sc1[f] * conv1_w[f * K1c + k];
    }
    if (tid < 16) d_bc[tid] = sh1[tid];
    // folded attention vectors: A[head][f] = sum_fo W[f][head*8+fo]*asrc[head][fo]
    if (tid < 64) {
        int head = tid >> 4, f = tid & 15;
        float sa = 0.f, sd = 0.f;
        #pragma unroll
        for (int fo = 0; fo < FOc; fo++) {
            float wv = s_gw[f * 32 + head * FOc + fo];
            sa = fmaf(wv, gat_asrc[head * FOc + fo], sa);
            sd = fmaf(wv, gat_adst[head * FOc + fo], sd);
        }
        d_A[head * 16 + f]  = sa;
        d_Dv[head * 16 + f] = sd;
    }
    // forward + reverse CSR (order-preserving, 4 threads/vertex)
    const int* src = sedge;
    const int* dst = sedge + E;
    const int qsz = (E + 3) >> 2;
    const int v = tid >> 2, q = tid & 3;
    const int lo = q * qsz;
    const int hi = min(E, lo + qsz);
    {
        int c = 0, rc = 0;
        for (int e = lo; e < hi; e++) { c += (dst[e] == v); rc += (src[e] == v); }
        cnt4[v][q] = c; rcnt4[v][q] = rc;
    }
    __syncthreads();
    if (tid == 0) {
        int off = 0, roff = 0;
        for (int vv = 0; vv < Vc; vv++) {
            soff[vv] = off;   off  += cnt4[vv][0] + cnt4[vv][1] + cnt4[vv][2] + cnt4[vv][3];
            rsoff[vv] = roff; roff += rcnt4[vv][0] + rcnt4[vv][1] + rcnt4[vv][2] + rcnt4[vv][3];
        }
        soff[Vc] = off; rsoff[Vc] = roff;
    }
    __syncthreads();
    if (tid <= Vc) { d_off[tid] = soff[tid]; d_roff[tid] = rsoff[tid]; }
    {
        int p = soff[v], rp = rsoff[v];
        for (int qq = 0; qq < 4; qq++) if (qq < q) { p += cnt4[v][qq]; rp += rcnt4[v][qq]; }
        for (int e = lo; e < hi; e++) {
            if (dst[e] == v) d_srcs[p++] = src[e];
            if (src[e] == v) d_rdst[rp++] = dst[e];
        }
    }
}

// ---------------- main: 16-ch conv + scalar-edge GAT (beta reformulation) ----------------
// smem floats:
//  xs[2560] | sW[512] sA[64] sD[64] sbias[32] | hbuf[8*1280] | est[8*544] edt[8*544]
//  invd[8*272] accs[8*68] | ints: soff[65] ssrc[512] roff[65] rdst[512]
#define OFF_W    XS_F
#define OFF_A    (OFF_W + 512)
#define OFF_D    (OFF_A + 64)
#define OFF_BIAS (OFF_D + 64)
#define OFF_H    (OFF_BIAS + 32)
#define OFF_EST  (OFF_H + NG * HG16)
#define OFF_EDT  (OFF_EST + NG * 544)
#define OFF_INV  (OFF_EDT + NG * 544)
#define OFF_ACC  (OFF_INV + NG * 272)
#define SM_FLOATS (OFF_ACC + NG * 68)
#define MAIN_SMEM (SM_FLOATS * 4 + (2 * (Vc + 1) + 2 * EMAX) * 4)

__global__ void __launch_bounds__(NTHR, 2)
main_kernel(const float* __restrict__ x,
            const float* __restrict__ gat_w,
            const float* __restrict__ bias_g,
            int E) {
    extern __shared__ float sm[];
    float* xs    = sm;
    float* sW    = sm + OFF_W;
    float* sA    = sm + OFF_A;
    float* sD    = sm + OFF_D;
    float* sbias = sm + OFF_BIAS;
    float* hbuf  = sm + OFF_H;                 // [g][v][H16]
    int*   soff  = (int*)(sm + SM_FLOATS);
    int*   ssrc  = soff + (Vc + 1);
    int*   sroff = ssrc + EMAX;
    int*   srdst = sroff + (Vc + 1);

    const int tid = threadIdx.x;
    const int bx  = blockIdx.x;
    const int b   = bx / (Tc / NG);
    const int t0  = (bx % (Tc / NG)) * NG;

    for (int idx = tid; idx < XS_F; idx += NTHR) {
        int v = idx / XROW, j = idx - v * XROW;
        int t = t0 - 15 + j;
        float val = 0.f;
        if (j < NG + 31 && t >= 0 && t < Tc) val = x[(b * Vc + v) * Tc + t];
        xs[idx] = val;
    }
    for (int i = tid; i < 512; i += NTHR) sW[i] = gat_w[i];
    if (tid < 64)  { sA[tid] = d_A[tid]; sD[tid] = d_Dv[tid]; }
    if (tid < 32)  sbias[tid] = bias_g[tid];
    for (int i = tid; i < Vc + 1; i += NTHR) { soff[i] = d_off[i]; sroff[i] = d_roff[i]; }
    for (int i = tid; i < E; i += NTHR) { ssrc[i] = d_srcs[i]; srdst[i] = d_rdst[i]; }
    __syncthreads();

    // ---- conv: 16 channels, f = tid&15, 24 slots over v ----
    {
        const int f = tid & 15;
        const int slot = tid >> 4;          // 0..23
        float w[K1c];
        #pragma unroll
        for (int k = 0; k < K1c; k++) w[k] = d_wc[k * 16 + f];
        const float cv = d_bc[f];
        const ull cvu = pack2(cv, cv);
        #pragma unroll 1
        for (int v = slot; v < 64; v += 24) {
            const float* xr = xs + v * XROW;
            ull pe[20];
            #pragma unroll
            for (int j = 0; j < 8; j++) pe[j] = *(const ull*)(xr + 2 * j);
            ull acc2[4], accO[5];
            #pragma unroll
            for (int p = 0; p < 4; p++) acc2[p] = cvu;
            #pragma unroll
            for (int q = 0; q < 5; q++) accO[q] = 0ULL;
            #pragma unroll
            for (int kh = 0; kh < 16; kh++) {
                if (kh < 12) pe[kh + 8] = *(const ull*)(xr + 2 * (kh + 8));
                const ull w0 = pack2(w[2 * kh],     w[2 * kh]);
                const ull w1 = pack2(w[2 * kh + 1], w[2 * kh + 1]);
                #pragma unroll
                for (int p = 0; p < 4; p++) fma2(acc2[p], w0, pe[kh + p]);
                #pragma unroll
                for (int q = 0; q < 5; q++) fma2(accO[q], w1, pe[kh + q]);
            }
            float elo[4], ehi[4], olo[5], ohi[5];
            #pragma unroll
            for (int p = 0; p < 4; p++) unpack2(acc2[p], elo[p], ehi[p]);
            #pragma unroll
            for (int q = 0; q < 5; q++) unpack2(accO[q], olo[q], ohi[q]);
            #pragma unroll
            for (int p = 0; p < 4; p++) {
                hbuf[(2 * p)     * HG16 + v * H16 + f] = elo[p] + ohi[p];
                hbuf[(2 * p + 1) * HG16 + v * H16 + f] = ehi[p] + olo[p + 1];
            }
        }
    }
    __syncthreads();

    // ---- GAT (warps 0..7): scalar edge passes + per-source 16-dim accumulation ----
    const int warp = tid >> 5, lane = tid & 31;
    if (warp < NG) {
        float*  h    = hbuf + warp * HG16;
        float2* est  = (float2*)(sm + OFF_EST) + warp * 272;   // [head*68 + v]
        float2* edt  = (float2*)(sm + OFF_EDT) + warp * 272;
        float*  invd = sm + OFF_INV + warp * 272;              // [head*68 + d]
        float*  accs = sm + OFF_ACC + warp * 68;               // [head*17 + f]

        // pass A: es/ed dots (16-dim) + exp tables
        #pragma unroll
        for (int i = 0; i < 8; i++) {
            int p = lane + 32 * i;
            int head = p & 3, v = p >> 2;
            const float4* hv = (const float4*)(h + v * H16);
            const float4* Ap = (const float4*)(sA + head * 16);
            const float4* Dp = (const float4*)(sD + head * 16);
            float es = 0.f, ed = 0.f;
            #pragma unroll
            for (int j = 0; j < 4; j++) {
                float4 hq = hv[j], aq = Ap[j], dq = Dp[j];
                es = fmaf(hq.x, aq.x, fmaf(hq.y, aq.y, fmaf(hq.z, aq.z, fmaf(hq.w, aq.w, es))));
                ed = fmaf(hq.x, dq.x, fmaf(hq.y, dq.y, fmaf(hq.z, dq.z, fmaf(hq.w, dq.w, ed))));
            }
            est[head * 68 + v] = make_float2(__expf(es), __expf(0.2f * es));
            edt[head * 68 + v] = make_float2(__expf(ed), __expf(0.2f * ed));
        }
        __syncwarp();

        const int head = lane & 3;
        // pass B: denominators (scalar edge loop over forward CSR)
        #pragma unroll 1
        for (int i = 0; i < 8; i++) {
            const int d = (lane >> 2) + 8 * i;
            const float2 Dd = edt[head * 68 + d];
            const int beg = soff[d], end = soff[d + 1];
            float den = 0.f;
            for (int e = beg; e < end; e++) {
                float2 Es = est[head * 68 + ssrc[e]];
                float p = Es.x * Dd.x;
                den += (p > 1.f) ? p : Es.y * Dd.y;
            }
            invd[head * 68 + d] = __frcp_rn(den);
        }
        __syncwarp();

        // pass C: beta per source (reverse CSR, scalar), then 16-dim accumulate
        ull acc8[8];
        #pragma unroll
        for (int j = 0; j < 8; j++) acc8[j] = 0ULL;
        #pragma unroll 1
        for (int i = 0; i < 8; i++) {
            const int s = (lane >> 2) + 8 * i;
            const float2 Es = est[head * 68 + s];
            const int beg = sroff[s], end = sroff[s + 1];
            float beta = 0.f;
            for (int e = beg; e < end; e++) {
                int d = srdst[e];
                float2 Dd = edt[head * 68 + d];
                float p = Es.x * Dd.x;
                float wexp = (p > 1.f) ? p : Es.y * Dd.y;
                beta = fmaf(wexp, invd[head * 68 + d], beta);
            }
            const ull bp = pack2(beta, beta);
            const ull* hs = (const ull*)(h + s * H16);
            #pragma unroll
            for (int j = 0; j < 8; j++) fma2(acc8[j], bp, hs[j]);
        }
        // reduce over the 8 lanes sharing head (lane bits 2..4)
        float a16[16];
        #pragma unroll
        for (int j = 0; j < 8; j++) unpack2(acc8[j], a16[2 * j], a16[2 * j + 1]);
        #pragma unroll
        for (int o = 0; o < 16; o++) {
            a16[o] += __shfl_xor_sync(0xffffffffu, a16[o], 4);
            a16[o] += __shfl_xor_sync(0xffffffffu, a16[o], 8);
            a16[o] += __shfl_xor_sync(0xffffffffu, a16[o], 16);
        }
        if (lane < 4) {
            #pragma unroll
            for (int f2 = 0; f2 < 16; f2++) accs[lane * 17 + f2] = a16[f2];
        }
        __syncwarp();

        // final projection 16 -> 32 and coalesced gbuf write
        {
            const int ho = lane;
            const int hd = lane >> 3;
            float m = 0.f;
            #pragma unroll
            for (int f2 = 0; f2 < 16; f2++)
                m = fmaf(sW[f2 * 32 + ho], accs[hd * 17 + f2], m);
            const int t = t0 + warp;
            d_gbuf[(b * Tc + t) * 32 + ho] = m * (1.0f / 64.0f) + sbias[ho];
        }
    }
}

// ---------------- tail ----------------
#define TP 192
#define TAIL_SMEM ((F2c * F2c * K3c + F2c * 40 + F2c * 24) * 4)

__global__ void __launch_bounds__(256)
tail_kernel(const float* __restrict__ conv3_w, float* __restrict__ out) {
    extern __shared__ float sm[];
    float* w3s   = sm;
    float* ptile = w3s + F2c * F2c * K3c;
    float* ytile = ptile + F2c * 40;

    const int tid = threadIdx.x;
    const int b = blockIdx.x;
    const int tile = blockIdx.y;
    const int tc0 = tile * 24;

    for (int i = tid; i < F2c * F2c * K3c; i += 256) w3s[i] = conv3_w[i];
    for (int i = tid; i < F2c * 40; i += 256) {
        int fi = i & 31, j = i >> 5;
        int tc = tc0 - 7 + j;
        float val = 0.f;
        if (j < 39 && tc >= 0 && tc < TP) {
            float scv = d_scale2[fi], shv = d_shift2[fi];
            float s = 0.f;
            #pragma unroll
            for (int r = 0; r < 8; r++) {
                float gv = fmaf(scv, d_gbuf[(b * Tc + tc * 8 + r) * 32 + fi], shv);
                s += gv > 0.f ? gv : (__expf(gv) - 1.f);
            }
            val = s * 0.125f;
        }
        ptile[fi * 40 + j] = val;
    }
    __syncthreads();

    for (int oidx = tid; oidx < F2c * 24; oidx += 256) {
        int fo = oidx / 24;
        int tcl = oidx - fo * 24;
        float acc = 0.f;
        for (int fi = 0; fi < F2c; fi++) {
            const float* wr = w3s + (fo * 32 + fi) * 16;
            const float* pr = ptile + fi * 40 + tcl;
            #pragma unroll
            for (int k = 0; k < K3c; k++) acc = fmaf(wr[k], pr[k], acc);
        }
        float z = fmaf(d_scale3[fo], acc, d_shift3[fo]);
        z = z > 0.f ? z : (__expf(z) - 1.f);
        ytile[fo * 24 + tcl] = z;
    }
    __syncthreads();

    for (int i = tid; i < F2c * 6; i += 256) {
        int fo = i / 6, tl = i - fo * 6;
        const float* yr = ytile + fo * 24 + tl * 4;
        float s = 0.25f * (yr[0] + yr[1] + yr[2] + yr[3]);
        out[(b * 32 + fo) * 48 + tile * 6 + tl] = s;
    }
}

// pad launches: keep main_kernel at captured launch index 3
__global__ void prof_pad_kernel() {}

// ---------------- launch ----------------
extern "C" void kernel_launch(void* const* d_in, const int* in_sizes, int n_in,
                              void* d_out, int out_size) {
    const float* x        = (const float*)d_in[0];
    const float* conv1_w  = (const float*)d_in[1];
    const float* bn1_g    = (const float*)d_in[2];
    const float* bn1_b    = (const float*)d_in[3];
    const float* bn1_m    = (const float*)d_in[4];
    const float* bn1_v    = (const float*)d_in[5];
    const float* gat_w    = (const float*)d_in[6];
    const float* gat_asrc = (const float*)d_in[7];
    const float* gat_adst = (const float*)d_in[8];
    const float* gat_bias = (const float*)d_in[9];
    const float* bn2_g    = (const float*)d_in[10];
    const float* bn2_b    = (const float*)d_in[11];
    const float* bn2_m    = (const float*)d_in[12];
    const float* bn2_v    = (const float*)d_in[13];
    const float* conv3_w  = (const float*)d_in[14];
    const float* bn3_g    = (const float*)d_in[15];
    const float* bn3_b    = (const float*)d_in[16];
    const float* bn3_m    = (const float*)d_in[17];
    const float* bn3_v    = (const float*)d_in[18];
    const int*   edge_idx = (const int*)d_in[19];
    int E = in_sizes[19] / 2;
    if (E > EMAX) E = EMAX;

    cudaFuncSetAttribute(main_kernel, cudaFuncAttributeMaxDynamicSharedMemorySize, MAIN_SMEM);
    cudaFuncSetAttribute(tail_kernel, cudaFuncAttributeMaxDynamicSharedMemorySize, TAIL_SMEM);

    setup_kernel<<<1, 256>>>(conv1_w, bn1_g, bn1_b, bn1_m, bn1_v, gat_w,
                             gat_asrc, gat_adst,
                             bn2_g, bn2_b, bn2_m, bn2_v,
                             bn3_g, bn3_b, bn3_m, bn3_v, edge_idx, E);
    prof_pad_kernel<<<1, 1>>>();
    prof_pad_kernel<<<1, 1>>>();
    main_kernel<<<Bc * (Tc / NG), NTHR, MAIN_SMEM>>>(x, gat_w, gat_bias, E);
    tail_kernel<<<dim3(Bc, 8), 256, TAIL_SMEM>>>(conv3_w, (float*)d_out);
}